// round 7
// baseline (speedup 1.0000x reference)
#include <cuda_runtime.h>
#include <cuda_bf16.h>

#define B_   256
#define T_   250
#define NS   2048
#define H_   256
#define G3   768
#define NSEL 50
#define UBv  0.1f
#define RITER 32

// ---------------- scratch (device globals; no runtime alloc) ----------------
__device__ float g_xg[(size_t)T_ * B_ * G3];     // xg0, later reused as xg1
__device__ float g_hseq[(size_t)T_ * B_ * H_];   // hidden sequence (reused by layer 1)
__device__ float g_att[B_ * NS];
__device__ float g_log[B_ * NS];
__device__ unsigned long long g_slots[128];      // grid-barrier slots

// bf16 3-way split planes (A reused for x [64000x2048] then hseq [64000x256])
__device__ uint4 g_a0[16384000];
__device__ uint4 g_a1[16384000];
__device__ uint4 g_a2[16384000];
__device__ uint4 g_w0[196608];
__device__ uint4 g_w1[196608];
__device__ uint4 g_w2[196608];

__device__ __forceinline__ float sigmf(float x) { return 1.f / (1.f + expf(-x)); }

// packed fp32x2 helpers — identical numerics to two scalar rn-FMAs
__device__ __forceinline__ unsigned long long dupf(float x) {
    unsigned long long r;
    asm("mov.b64 %0, {%1, %1};" : "=l"(r) : "f"(x));
    return r;
}
#define FFMA2(d, a, b) asm("fma.rn.f32x2 %0, %1, %2, %0;" : "+l"(d) : "l"(a), "l"(b))
#define FADD2(d, a)    asm("add.rn.f32x2 %0, %0, %1;"     : "+l"(d) : "l"(a))
__device__ __forceinline__ void unpack2(unsigned long long v, float& lo, float& hi) {
    asm("mov.b64 {%0, %1}, %2;" : "=f"(lo), "=f"(hi) : "l"(v));
}

// ============================================================================
// bf16 3-way split conversion
// ============================================================================
__device__ __forceinline__ void split3(float f, unsigned& h0, unsigned& h1, unsigned& h2) {
    __nv_bfloat16 b0 = __float2bfloat16_rn(f);
    float r1 = f - __bfloat162float(b0);
    __nv_bfloat16 b1 = __float2bfloat16_rn(r1);
    float r2 = r1 - __bfloat162float(b1);
    __nv_bfloat16 b2 = __float2bfloat16_rn(r2);
    h0 = (unsigned)__bfloat16_as_ushort(b0);
    h1 = (unsigned)__bfloat16_as_ushort(b1);
    h2 = (unsigned)__bfloat16_as_ushort(b2);
}

__device__ __forceinline__ void split4v(float4 v, uint2& o0, uint2& o1, uint2& o2) {
    float f[4] = {v.x, v.y, v.z, v.w};
    unsigned a[4], b[4], c[4];
#pragma unroll
    for (int i = 0; i < 4; ++i) split3(f[i], a[i], b[i], c[i]);
    o0.x = a[0] | (a[1] << 16); o0.y = a[2] | (a[3] << 16);
    o1.x = b[0] | (b[1] << 16); o1.y = b[2] | (b[3] << 16);
    o2.x = c[0] | (c[1] << 16); o2.y = c[2] | (c[3] << 16);
}

// x[b][t][k] -> planes[m=t*256+b][k]
__global__ void conv_x3_kernel(const float* __restrict__ x,
                               uint2* __restrict__ p0, uint2* __restrict__ p1,
                               uint2* __restrict__ p2)
{
    const size_t total = (size_t)64000 * 512;
    for (size_t u = (size_t)blockIdx.x * blockDim.x + threadIdx.x; u < total;
         u += (size_t)gridDim.x * blockDim.x) {
        const int m = (int)(u >> 9);
        const int k4 = (int)(u & 511);
        const int b = m & 255, t = m >> 8;
        float4 v = *(const float4*)(x + ((size_t)b * T_ + t) * 2048 + (size_t)k4 * 4);
        uint2 o0, o1, o2; split4v(v, o0, o1, o2);
        p0[u] = o0; p1[u] = o1; p2[u] = o2;
    }
}

__global__ void conv_p3_kernel(const float* __restrict__ src,
                               uint2* __restrict__ p0, uint2* __restrict__ p1,
                               uint2* __restrict__ p2, size_t n4)
{
    for (size_t u = (size_t)blockIdx.x * blockDim.x + threadIdx.x; u < n4;
         u += (size_t)gridDim.x * blockDim.x) {
        float4 v = ((const float4*)src)[u];
        uint2 o0, o1, o2; split4v(v, o0, o1, o2);
        p0[u] = o0; p1[u] = o1; p2[u] = o2;
    }
}

// ============================================================================
// Tensor-core GEMM: C[M,N] = A[M,K] @ W[N,K]^T + bias  (bf16 3-split, fp32 acc)
// Tile 128x128x64, 256 thr (8 warps = 4m x 2n), cp.async double buffer.
// smem per array: [128 rows][64 bf16]=[128][8 uint4], phys col = c ^ (row&7).
// ============================================================================
#define TC_BUF   98304                    // 6 arrays x 16384 B
#define TC_SMEM  (2 * TC_BUF)             // 196608

__device__ __forceinline__ void ldsm4(unsigned r[4], unsigned addr) {
    asm volatile("ldmatrix.sync.aligned.m8n8.x4.shared.b16 {%0,%1,%2,%3}, [%4];"
                 : "=r"(r[0]), "=r"(r[1]), "=r"(r[2]), "=r"(r[3]) : "r"(addr));
}
__device__ __forceinline__ void mma_bf16(float* c, const unsigned* a, const unsigned* b) {
    asm volatile("mma.sync.aligned.m16n8k16.row.col.f32.bf16.bf16.f32 "
                 "{%0,%1,%2,%3}, {%4,%5,%6,%7}, {%8,%9}, {%0,%1,%2,%3};"
                 : "+f"(c[0]), "+f"(c[1]), "+f"(c[2]), "+f"(c[3])
                 : "r"(a[0]), "r"(a[1]), "r"(a[2]), "r"(a[3]), "r"(b[0]), "r"(b[1]));
}

__device__ __forceinline__ void tc_stage(const uint4* const gsrc[6], int ku4, int tid,
                                         unsigned sbuf, int it)
{
    const int k0 = it * 8;
#pragma unroll
    for (int arr = 0; arr < 6; ++arr) {
#pragma unroll
        for (int q = 0; q < 4; ++q) {
            const int idx = tid + q * 256;
            const int row = idx >> 3, c = idx & 7;
            const uint4* g = gsrc[arr] + (size_t)row * ku4 + k0 + c;
            unsigned s = sbuf + arr * 16384 + row * 128 + ((c ^ (row & 7)) << 4);
            asm volatile("cp.async.cg.shared.global [%0], [%1], 16;" :: "r"(s), "l"(g));
        }
    }
    asm volatile("cp.async.commit_group;");
}

__device__ __forceinline__ void tc_compute(unsigned sbuf, int wm, int wn,
                                           int lrow, int tb0, int tb1,
                                           float acc[2][8][4])
{
#pragma unroll
    for (int ks = 0; ks < 4; ++ks) {
        unsigned af[3][2][4];
        const unsigned pcA = (unsigned)(((ks * 2 + tb1) ^ lrow) << 4);
#pragma unroll
        for (int s = 0; s < 3; ++s)
#pragma unroll
            for (int i = 0; i < 2; ++i) {
                const int row = wm * 32 + i * 16 + lrow + tb0 * 8;
                ldsm4(af[s][i], sbuf + s * 16384 + row * 128 + pcA);
            }
        const unsigned pcB = (unsigned)(((ks * 2 + tb0) ^ lrow) << 4);
#pragma unroll
        for (int hh = 0; hh < 2; ++hh) {
            unsigned bfr[3][4][2];
#pragma unroll
            for (int s = 0; s < 3; ++s)
#pragma unroll
                for (int p = 0; p < 2; ++p) {
                    const int row = wn * 64 + (hh * 2 + p) * 16 + lrow + tb1 * 8;
                    unsigned r[4];
                    ldsm4(r, sbuf + 49152 + s * 16384 + row * 128 + pcB);
                    bfr[s][2 * p][0] = r[0];     bfr[s][2 * p][1] = r[1];
                    bfr[s][2 * p + 1][0] = r[2]; bfr[s][2 * p + 1][1] = r[3];
                }
#pragma unroll
            for (int i = 0; i < 2; ++i)
#pragma unroll
                for (int n = 0; n < 4; ++n) {
                    float* c = acc[i][hh * 4 + n];
                    mma_bf16(c, af[0][i], bfr[0][n]);   // hi*hi
                    mma_bf16(c, af[0][i], bfr[1][n]);   // hi*mid
                    mma_bf16(c, af[1][i], bfr[0][n]);   // mid*hi
                    mma_bf16(c, af[0][i], bfr[2][n]);   // hi*lo
                    mma_bf16(c, af[2][i], bfr[0][n]);   // lo*hi
                    mma_bf16(c, af[1][i], bfr[1][n]);   // mid*mid
                }
        }
    }
}

__global__ void __launch_bounds__(256) tc_gemm_kernel(
    const uint4* __restrict__ a0, const uint4* __restrict__ a1, const uint4* __restrict__ a2,
    const uint4* __restrict__ w0, const uint4* __restrict__ w1, const uint4* __restrict__ w2,
    const float* __restrict__ bias, float* __restrict__ C, int N, int K)
{
    extern __shared__ uint4 tcsm[];
    const unsigned sb = (unsigned)__cvta_generic_to_shared(tcsm);
    const int tid = threadIdx.x;
    const int m0 = blockIdx.y * 128, n0 = blockIdx.x * 128;
    const int ku4 = K >> 3;
    const int nIter = K >> 6;

    const uint4* gsrc[6] = {
        a0 + (size_t)m0 * ku4, a1 + (size_t)m0 * ku4, a2 + (size_t)m0 * ku4,
        w0 + (size_t)n0 * ku4, w1 + (size_t)n0 * ku4, w2 + (size_t)n0 * ku4 };

    const int warp = tid >> 5, l = tid & 31;
    const int wm = warp & 3, wn = warp >> 2;
    const int lrow = l & 7, tb0 = (l >> 3) & 1, tb1 = (l >> 4) & 1;

    float acc[2][8][4] = {};

    tc_stage(gsrc, ku4, tid, sb, 0);
    for (int it = 0; it < nIter; ++it) {
        asm volatile("cp.async.wait_group 0;");
        __syncthreads();
        if (it + 1 < nIter)
            tc_stage(gsrc, ku4, tid, sb + (unsigned)(((it + 1) & 1) * TC_BUF), it + 1);
        tc_compute(sb + (unsigned)((it & 1) * TC_BUF), wm, wn, lrow, tb0, tb1, acc);
        __syncthreads();
    }

    const int g = l >> 2, tq = (l & 3) * 2;
#pragma unroll
    for (int i = 0; i < 2; ++i)
#pragma unroll
        for (int n = 0; n < 8; ++n) {
            const int row = m0 + wm * 32 + i * 16 + g;
            const int col = n0 + wn * 64 + n * 8 + tq;
            const float b0 = bias[col], b1 = bias[col + 1];
            C[(size_t)row * N + col]           = acc[i][n][0] + b0;
            C[(size_t)row * N + col + 1]       = acc[i][n][1] + b1;
            C[(size_t)(row + 8) * N + col]     = acc[i][n][2] + b0;
            C[(size_t)(row + 8) * N + col + 1] = acc[i][n][3] + b1;
        }
}

// ============================================================================
// fp32 FFMA2 GEMM (kept for the two small head GEMMs, act 1/2)
// ============================================================================
#define BM 128
#define BN 128
#define BK 16
#define ASTR 132
#define WSTR 140
__device__ __forceinline__ int wphys(int c) { return c + ((c >> 5) << 2); }

__device__ __forceinline__ void gemm_tile_compute(
    const float* __restrict__ As, const float* __restrict__ Ws,
    unsigned long long acc2[4][8], int tm, int wcol)
{
#pragma unroll
    for (int k = 0; k < BK; ++k) {
        ulonglong2 a01 = *(const ulonglong2*)&As[k * ASTR + tm * 8];
        ulonglong2 a23 = *(const ulonglong2*)&As[k * ASTR + tm * 8 + 4];
        float4 w0 = *(const float4*)&Ws[k * WSTR + wcol];
        float4 w1 = *(const float4*)&Ws[k * WSTR + wcol + 4];
        unsigned long long wd[8];
        wd[0] = dupf(w0.x); wd[1] = dupf(w0.y); wd[2] = dupf(w0.z); wd[3] = dupf(w0.w);
        wd[4] = dupf(w1.x); wd[5] = dupf(w1.y); wd[6] = dupf(w1.z); wd[7] = dupf(w1.w);
#pragma unroll
        for (int j = 0; j < 8; ++j) {
            FFMA2(acc2[0][j], a01.x, wd[j]);
            FFMA2(acc2[1][j], a01.y, wd[j]);
            FFMA2(acc2[2][j], a23.x, wd[j]);
            FFMA2(acc2[3][j], a23.y, wd[j]);
        }
    }
}

__global__ void __launch_bounds__(256, 2) gemm_kernel(
    const float* __restrict__ A, const float* __restrict__ W,
    const float* __restrict__ bias, float* __restrict__ C,
    int M, int N, int K, int act)
{
    __shared__ float As[2][BK * ASTR];
    __shared__ float Ws[2][BK * WSTR];
    const int tid = threadIdx.x;
    const int m0 = blockIdx.y * BM;
    const int n0 = blockIdx.x * BN;

    const int lr = tid >> 2;
    const int lk = (tid & 3) << 2;

    const float* pa0 = A + (long long)(m0 + lr) * K + lk;
    const float* pa1 = A + (long long)(m0 + lr + 64) * K + lk;
    const float* pw0 = W + (long long)(n0 + lr) * K + lk;
    const float* pw1 = W + (long long)(n0 + lr + 64) * K + lk;

    const int tm = tid >> 4;
    const int tn = tid & 15;
    const int wcol = tn * 8 + ((tn >> 2) << 2);
    const int wc0 = wphys(lr);
    const int wc1 = wphys(lr + 64);

    unsigned long long acc2[4][8];
#pragma unroll
    for (int i = 0; i < 4; ++i)
#pragma unroll
        for (int j = 0; j < 8; ++j) acc2[i][j] = 0ULL;

    {
        float4 a0 = *(const float4*)pa0;
        float4 a1 = *(const float4*)pa1;
        float4 w0 = *(const float4*)pw0;
        float4 w1 = *(const float4*)pw1;
        float av0[4] = {a0.x, a0.y, a0.z, a0.w};
        float av1[4] = {a1.x, a1.y, a1.z, a1.w};
        float wv0[4] = {w0.x, w0.y, w0.z, w0.w};
        float wv1[4] = {w1.x, w1.y, w1.z, w1.w};
#pragma unroll
        for (int j = 0; j < 4; ++j) {
            As[0][(lk + j) * ASTR + lr]      = av0[j];
            As[0][(lk + j) * ASTR + lr + 64] = av1[j];
            Ws[0][(lk + j) * WSTR + wc0]     = wv0[j];
            Ws[0][(lk + j) * WSTR + wc1]     = wv1[j];
        }
    }
    __syncthreads();

    const int nCh = K / BK;
    for (int c = 1; c < nCh; ++c) {
        const int off = c * BK;
        float4 na0 = *(const float4*)(pa0 + off);
        float4 na1 = *(const float4*)(pa1 + off);
        float4 nw0 = *(const float4*)(pw0 + off);
        float4 nw1 = *(const float4*)(pw1 + off);

        gemm_tile_compute(As[(c - 1) & 1], Ws[(c - 1) & 1], acc2, tm, wcol);

        const int wb = c & 1;
        float av0[4] = {na0.x, na0.y, na0.z, na0.w};
        float av1[4] = {na1.x, na1.y, na1.z, na1.w};
        float wv0[4] = {nw0.x, nw0.y, nw0.z, nw0.w};
        float wv1[4] = {nw1.x, nw1.y, nw1.z, nw1.w};
#pragma unroll
        for (int j = 0; j < 4; ++j) {
            As[wb][(lk + j) * ASTR + lr]      = av0[j];
            As[wb][(lk + j) * ASTR + lr + 64] = av1[j];
            Ws[wb][(lk + j) * WSTR + wc0]     = wv0[j];
            Ws[wb][(lk + j) * WSTR + wc1]     = wv1[j];
        }
        __syncthreads();
    }
    gemm_tile_compute(As[(nCh - 1) & 1], Ws[(nCh - 1) & 1], acc2, tm, wcol);

#pragma unroll
    for (int p = 0; p < 4; ++p) {
        float rowlo[8], rowhi[8];
#pragma unroll
        for (int j = 0; j < 8; ++j) {
            float lo, hi; unpack2(acc2[p][j], lo, hi);
            float bj = bias[n0 + tn * 8 + j];
            lo += bj; hi += bj;
            if (act == 1)      { lo = sigmf(lo); hi = sigmf(hi); }
            else if (act == 2) { lo = lo * sigmf(lo); hi = hi * sigmf(hi); }
            rowlo[j] = lo; rowhi[j] = hi;
        }
        const long long mA = m0 + tm * 8 + 2 * p;
        float* c0 = &C[mA * N + n0 + tn * 8];
        float* c1 = &C[(mA + 1) * N + n0 + tn * 8];
        *(float4*)c0       = make_float4(rowlo[0], rowlo[1], rowlo[2], rowlo[3]);
        *(float4*)(c0 + 4) = make_float4(rowlo[4], rowlo[5], rowlo[6], rowlo[7]);
        *(float4*)c1       = make_float4(rowhi[0], rowhi[1], rowhi[2], rowhi[3]);
        *(float4*)(c1 + 4) = make_float4(rowhi[4], rowhi[5], rowhi[6], rowhi[7]);
    }
}

// ============================================================================
// Persistent GRU scan (contention-free slot barrier)
// ============================================================================
#define GRU_W2_ULL   (3 * 256 * 16)
#define GRU_HT_F     (256 * 36)
#define GRU_PART_ULL (3 * 64 * 12)
#define GRU_SMEM     (GRU_W2_ULL * 8 + GRU_HT_F * 4 + GRU_PART_ULL * 8)

__global__ void __launch_bounds__(256, 1) gru_scan_kernel(
    const float* __restrict__ Whh, const float* __restrict__ bhh,
    const float* __restrict__ xg, float* __restrict__ hseq)
{
    extern __shared__ char smraw[];
    unsigned long long* w2  = (unsigned long long*)smraw;
    float*              hT  = (float*)(smraw + GRU_W2_ULL * 8);
    unsigned long long* prt = (unsigned long long*)(smraw + GRU_W2_ULL * 8 + GRU_HT_F * 4);

    const int tid = threadIdx.x;
    const int b0 = (blockIdx.x >> 4) * 32;
    const int h0 = (blockIdx.x & 15) * 16;
    const int c  = tid & 15;
    const int g  = (tid >> 4) & 3;
    const int ks = tid >> 6;
    const int r0 = g * 8;
    const int slot = (g << 4) | c;

    for (int idx = tid; idx < 48 * 64; idx += 256) {
        const int row = idx >> 6;
        const int k4  = (idx & 63) << 2;
        const int gate = row >> 4, cc = row & 15;
        float4 wv = *(const float4*)(Whh + (size_t)(gate * H_ + h0 + cc) * H_ + k4);
        w2[(gate * 256 + k4 + 0) * 16 + cc] = dupf(wv.x);
        w2[(gate * 256 + k4 + 1) * 16 + cc] = dupf(wv.y);
        w2[(gate * 256 + k4 + 2) * 16 + cc] = dupf(wv.z);
        w2[(gate * 256 + k4 + 3) * 16 + cc] = dupf(wv.w);
    }
    __syncthreads();

    const int hg = h0 + c;
    const float br = bhh[hg], bz = bhh[H_ + hg], bn = bhh[2 * H_ + hg];
    const int lr  = tid & 31;
    const int lk0 = (tid >> 5) * 32;

    for (int t = 0; t < T_; ++t) {
        unsigned long long aR[4] = {0, 0, 0, 0}, aZ[4] = {0, 0, 0, 0}, aN[4] = {0, 0, 0, 0};
        float xv[3][8];

        if (ks == 0) {
            const float* xrow = xg + (size_t)t * (B_ * G3);
#pragma unroll
            for (int i = 0; i < 8; ++i) {
                const float* xr = xrow + (size_t)(b0 + r0 + i) * G3;
                xv[0][i] = xr[hg];
                xv[1][i] = xr[H_ + hg];
                xv[2][i] = xr[2 * H_ + hg];
            }
        }

        if (t > 0) {
            const float* src = hseq + (size_t)(t - 1) * (B_ * H_)
                                    + (size_t)(b0 + lr) * H_ + lk0;
#pragma unroll
            for (int q = 0; q < 8; ++q) {
                float4 v = __ldcg((const float4*)(src + q * 4));
                const int k = lk0 + q * 4;
                hT[(k + 0) * 36 + lr] = v.x;
                hT[(k + 1) * 36 + lr] = v.y;
                hT[(k + 2) * 36 + lr] = v.z;
                hT[(k + 3) * 36 + lr] = v.w;
            }
            __syncthreads();

            const int kb = ks * 64;
#pragma unroll 4
            for (int kk = 0; kk < 64; ++kk) {
                const int k = kb + kk;
                ulonglong2 a01 = *(const ulonglong2*)&hT[k * 36 + r0];
                ulonglong2 a23 = *(const ulonglong2*)&hT[k * 36 + r0 + 4];
                unsigned long long wr = w2[k * 16 + c];
                unsigned long long wz = w2[(256 + k) * 16 + c];
                unsigned long long wn = w2[(512 + k) * 16 + c];
                FFMA2(aR[0], a01.x, wr); FFMA2(aR[1], a01.y, wr);
                FFMA2(aR[2], a23.x, wr); FFMA2(aR[3], a23.y, wr);
                FFMA2(aZ[0], a01.x, wz); FFMA2(aZ[1], a01.y, wz);
                FFMA2(aZ[2], a23.x, wz); FFMA2(aZ[3], a23.y, wz);
                FFMA2(aN[0], a01.x, wn); FFMA2(aN[1], a01.y, wn);
                FFMA2(aN[2], a23.x, wn); FFMA2(aN[3], a23.y, wn);
            }

            if (ks != 0) {
                unsigned long long* p = prt + ((ks - 1) * 64 + slot) * 12;
#pragma unroll
                for (int i = 0; i < 4; ++i) { p[i] = aR[i]; p[4 + i] = aZ[i]; p[8 + i] = aN[i]; }
            }
            __syncthreads();
            if (ks == 0) {
#pragma unroll
                for (int q = 0; q < 3; ++q) {
                    const unsigned long long* p = prt + (q * 64 + slot) * 12;
#pragma unroll
                    for (int i = 0; i < 4; ++i) {
                        FADD2(aR[i], p[i]); FADD2(aZ[i], p[4 + i]); FADD2(aN[i], p[8 + i]);
                    }
                }
            }
        }

        if (ks == 0) {
            float rr[8], zz[8], nn[8], hold[8];
#pragma unroll
            for (int i = 0; i < 4; ++i) {
                unpack2(aR[i], rr[2 * i], rr[2 * i + 1]);
                unpack2(aZ[i], zz[2 * i], zz[2 * i + 1]);
                unpack2(aN[i], nn[2 * i], nn[2 * i + 1]);
            }
#pragma unroll
            for (int i = 0; i < 8; ++i)
                hold[i] = (t > 0) ? hT[hg * 36 + r0 + i] : 0.f;

            float* hout = hseq + (size_t)t * (B_ * H_);
#pragma unroll
            for (int i = 0; i < 8; ++i) {
                const float r = sigmf(xv[0][i] + rr[i] + br);
                const float z = sigmf(xv[1][i] + zz[i] + bz);
                const float n = tanhf(xv[2][i] + r * (nn[i] + bn));
                hout[(size_t)(b0 + r0 + i) * H_ + hg] = (1.f - z) * n + z * hold[i];
            }
        }

        if (t < T_ - 1) {
            __threadfence();
            __syncthreads();
            if (tid == 0)
                *((volatile unsigned long long*)&g_slots[blockIdx.x]) =
                    (unsigned long long)(t + 1);
            if (tid < 128) {
                volatile unsigned long long* s =
                    (volatile unsigned long long*)&g_slots[tid];
                while (*s <= (unsigned long long)t) { }
            }
            __threadfence();
            __syncthreads();
        }
    }
}

__global__ void reset_sync_kernel() {
    if (threadIdx.x < 128) g_slots[threadIdx.x] = 0ULL;
}

// ============================================================================
// Finalize per batch row: top-50 -> mask; softmax; mask+normalize; rebalance.
// ============================================================================
__global__ void __launch_bounds__(256) finalize_kernel(
    const float* __restrict__ att, const float* __restrict__ logits,
    float* __restrict__ out)
{
    __shared__ float a_s[NS];
    __shared__ float w_s[NS];
    __shared__ unsigned char m_s[NS];
    __shared__ float rf[256];
    __shared__ float rb[256];
    __shared__ int   ri[256];
    __shared__ float sc[8];

    const int b = blockIdx.x;
    const int tid = threadIdx.x;

    for (int n = tid; n < NS; n += 256) {
        a_s[n] = att[(long long)b * NS + n];
        w_s[n] = logits[(long long)b * NS + n];
        m_s[n] = 0;
    }
    if (tid == 0) sc[4] = 0.f;
    __syncthreads();

    for (int it = 0; it < NSEL; ++it) {
        float bv = -3.402823466e38f; int bi = 0x7fffffff;
        for (int n = tid; n < NS; n += 256) {
            float v = a_s[n];
            if (v > bv) { bv = v; bi = n; }
        }
        rf[tid] = bv; ri[tid] = bi;
        __syncthreads();
        for (int s = 128; s > 0; s >>= 1) {
            if (tid < s) {
                float v2 = rf[tid + s]; int i2 = ri[tid + s];
                if (v2 > rf[tid] || (v2 == rf[tid] && i2 < ri[tid])) { rf[tid] = v2; ri[tid] = i2; }
            }
            __syncthreads();
        }
        if (tid == 0) { m_s[ri[0]] = 1; a_s[ri[0]] = -3.402823466e38f; }
        __syncthreads();
    }

    float lm = -3.402823466e38f;
    for (int n = tid; n < NS; n += 256) lm = fmaxf(lm, w_s[n]);
    rf[tid] = lm; __syncthreads();
    for (int s = 128; s > 0; s >>= 1) { if (tid < s) rf[tid] = fmaxf(rf[tid], rf[tid + s]); __syncthreads(); }
    const float Mx = rf[0];
    __syncthreads();

    float ps = 0.f;
    for (int n = tid; n < NS; n += 256) { float e = expf(w_s[n] - Mx); w_s[n] = e; ps += e; }
    rf[tid] = ps; __syncthreads();
    for (int s = 128; s > 0; s >>= 1) { if (tid < s) rf[tid] += rf[tid + s]; __syncthreads(); }
    const float S = rf[0];
    __syncthreads();

    float pm = 0.f;
    for (int n = tid; n < NS; n += 256) {
        float mw = m_s[n] ? (w_s[n] / S) : 0.f;
        w_s[n] = mw; pm += mw;
    }
    rf[tid] = pm; __syncthreads();
    for (int s = 128; s > 0; s >>= 1) { if (tid < s) rf[tid] += rf[tid + s]; __syncthreads(); }
    const float SM = rf[0];
    __syncthreads();

    for (int n = tid; n < NS; n += 256) {
        float w0 = w_s[n] / (SM + 1e-8f);
        a_s[n] = w0;
        w_s[n] = fminf(fmaxf(w0, 0.f), UBv);
    }
    __syncthreads();

    for (int it = 0; it < RITER; ++it) {
        float pl = 0.f, pn = 0.f; int ph = 0;
        for (int n = tid; n < NS; n += 256) {
            float w = w_s[n];
            int nm = (w != UBv) && m_s[n];
            pl += a_s[n] - w;
            if (nm) { pn += w; ph = 1; }
        }
        rf[tid] = pl; rb[tid] = pn; ri[tid] = ph;
        __syncthreads();
        for (int s = 128; s > 0; s >>= 1) {
            if (tid < s) { rf[tid] += rf[tid + s]; rb[tid] += rb[tid + s]; ri[tid] |= ri[tid + s]; }
            __syncthreads();
        }
        if (tid == 0) { sc[0] = rf[0]; sc[1] = rb[0]; sc[2] = ri[0] ? 1.f : 0.f; }
        __syncthreads();

        const float leftover = sc[0];
        const float nsum = sc[1];
        const bool hasnom = (sc[2] != 0.f);
        const bool done = (sc[4] != 0.f);
        const bool upd = (!done) && hasnom;
        const float denom = (nsum == 0.f) ? 1.f : nsum;

        int po = 0;
        for (int n = tid; n < NS; n += 256) {
            float w = w_s[n];
            int nm = (w != UBv) && m_s[n];
            float gift = (leftover * (nm ? w : 0.f)) / denom;
            float w1 = upd ? (w + gift) : w;
            if (w1 > UBv) po = 1;
            w_s[n] = w1;
            if (upd) a_s[n] = w1;
        }
        ri[tid] = po;
        __syncthreads();
        for (int s = 128; s > 0; s >>= 1) { if (tid < s) ri[tid] |= ri[tid + s]; __syncthreads(); }
        const bool over = (ri[0] != 0);
        __syncthreads();

        if (upd && over)
            for (int n = tid; n < NS; n += 256)
                w_s[n] = fminf(fmaxf(w_s[n], 0.f), UBv);
        if (tid == 0) {
            bool d = done || ((!done) && (!hasnom)) || (upd && (!over));
            sc[4] = d ? 1.f : 0.f;
        }
        __syncthreads();
    }

    for (int n = tid; n < NS; n += 256)
        out[(long long)b * NS + n] = w_s[n];
}

// ============================================================================
extern "C" void kernel_launch(void* const* d_in, const int* in_sizes, int n_in,
                              void* d_out, int out_size)
{
    (void)in_sizes; (void)n_in; (void)out_size;
    const float* x    = (const float*)d_in[0];
    const float* Wih0 = (const float*)d_in[1];
    const float* Whh0 = (const float*)d_in[2];
    const float* bih0 = (const float*)d_in[3];
    const float* bhh0 = (const float*)d_in[4];
    const float* Wih1 = (const float*)d_in[5];
    const float* Whh1 = (const float*)d_in[6];
    const float* bih1 = (const float*)d_in[7];
    const float* bhh1 = (const float*)d_in[8];
    const float* Wa   = (const float*)d_in[9];
    const float* ba   = (const float*)d_in[10];
    const float* Wf   = (const float*)d_in[11];
    const float* bf   = (const float*)d_in[12];
    float* out = (float*)d_out;

    float *xg, *hseq, *attb, *logb;
    uint4 *a0, *a1, *a2, *w0, *w1, *w2;
    cudaGetSymbolAddress((void**)&xg,   g_xg);
    cudaGetSymbolAddress((void**)&hseq, g_hseq);
    cudaGetSymbolAddress((void**)&attb, g_att);
    cudaGetSymbolAddress((void**)&logb, g_log);
    cudaGetSymbolAddress((void**)&a0, g_a0);
    cudaGetSymbolAddress((void**)&a1, g_a1);
    cudaGetSymbolAddress((void**)&a2, g_a2);
    cudaGetSymbolAddress((void**)&w0, g_w0);
    cudaGetSymbolAddress((void**)&w1, g_w1);
    cudaGetSymbolAddress((void**)&w2, g_w2);

    cudaFuncSetAttribute(gru_scan_kernel,
                         cudaFuncAttributeMaxDynamicSharedMemorySize, GRU_SMEM);
    cudaFuncSetAttribute(tc_gemm_kernel,
                         cudaFuncAttributeMaxDynamicSharedMemorySize, TC_SMEM);

    // ---- layer 0: convert, xg0 = A @ Wih0^T + bih0 (tensor cores) ----
    conv_x3_kernel<<<2048, 256>>>(x, (uint2*)a0, (uint2*)a1, (uint2*)a2);
    conv_p3_kernel<<<1536, 256>>>(Wih0, (uint2*)w0, (uint2*)w1, (uint2*)w2,
                                  (size_t)G3 * 2048 / 4);
    tc_gemm_kernel<<<dim3(G3 / 128, 500), 256, TC_SMEM>>>(
        a0, a1, a2, w0, w1, w2, bih0, xg, G3, 2048);

    reset_sync_kernel<<<1, 128>>>();
    gru_scan_kernel<<<128, 256, GRU_SMEM>>>(Whh0, bhh0, xg, hseq);

    // ---- layer 1: convert hseq, xg1 (tensor cores) ----
    conv_p3_kernel<<<2048, 256>>>(hseq, (uint2*)a0, (uint2*)a1, (uint2*)a2,
                                  (size_t)64000 * H_ / 4);
    conv_p3_kernel<<<192, 256>>>(Wih1, (uint2*)w0, (uint2*)w1, (uint2*)w2,
                                 (size_t)G3 * H_ / 4);
    tc_gemm_kernel<<<dim3(G3 / 128, 500), 256, TC_SMEM>>>(
        a0, a1, a2, w0, w1, w2, bih1, xg, G3, H_);

    reset_sync_kernel<<<1, 128>>>();
    gru_scan_kernel<<<128, 256, GRU_SMEM>>>(Whh1, bhh1, xg, hseq);

    const float* hT = hseq + (size_t)(T_ - 1) * B_ * H_;

    // heads (fp32 scalar path — accuracy-critical, tiny)
    gemm_kernel<<<dim3(NS / BN, B_ / BM), 256>>>(hT, Wa, ba, attb, B_, NS, H_, 1);
    gemm_kernel<<<dim3(NS / BN, B_ / BM), 256>>>(hT, Wf, bf, logb, B_, NS, H_, 2);

    finalize_kernel<<<B_, 256>>>(attb, logb, out);
}